// round 1
// baseline (speedup 1.0000x reference)
#include <cuda_runtime.h>
#include <math.h>

#define D 128
#define MAXN 100096
#define MAXE 1600256
#define EPSL 1e-5f

// ---------------- scratch (device globals: no allocation allowed) ----------------
__device__ float g_res[(size_t)MAXN * D];
__device__ float g_agg[(size_t)MAXN * D];
__device__ float g_h0 [(size_t)MAXN * D];
__device__ float g_h1 [(size_t)MAXN * D];
__device__ float g_invdeg[MAXN];
__device__ int   g_deg[MAXN];
__device__ int   g_rowptr[MAXN + 1];
__device__ int   g_cursor[MAXN];
__device__ int   g_scantmp[MAXN];
__device__ int   g_blksums[256];
__device__ int   g_srcsorted[MAXE];

// ---------------- CSR build ----------------
__global__ void k_zero(int* deg, int* rowptr, int N) {
    int i = blockIdx.x * blockDim.x + threadIdx.x;
    if (i < N) deg[i] = 0;
    if (i == 0) rowptr[0] = 0;
}

__global__ void k_count(const int* __restrict__ dst, int* __restrict__ deg, int E) {
    int e = blockIdx.x * blockDim.x + threadIdx.x;
    if (e < E) atomicAdd(&deg[dst[e]], 1);
}

__global__ void k_scan1(const int* __restrict__ deg, int* __restrict__ tmp,
                        int* __restrict__ blks, int N) {
    __shared__ int sm[1024];
    int i = blockIdx.x * 1024 + threadIdx.x;
    int v = (i < N) ? deg[i] : 0;
    sm[threadIdx.x] = v;
    __syncthreads();
    for (int o = 1; o < 1024; o <<= 1) {
        int t = (threadIdx.x >= o) ? sm[threadIdx.x - o] : 0;
        __syncthreads();
        sm[threadIdx.x] += t;
        __syncthreads();
    }
    if (i < N) tmp[i] = sm[threadIdx.x];
    if (threadIdx.x == 1023) blks[blockIdx.x] = sm[1023];
}

__global__ void k_scan2(int* blks, int nb) {
    if (threadIdx.x == 0 && blockIdx.x == 0) {
        int run = 0;
        for (int b = 0; b < nb; b++) { int t = blks[b]; blks[b] = run; run += t; }
    }
}

__global__ void k_scan3(const int* __restrict__ tmp, const int* __restrict__ blks,
                        int* __restrict__ rowptr, int N) {
    int i = blockIdx.x * 1024 + threadIdx.x;
    if (i < N) rowptr[i + 1] = tmp[i] + blks[blockIdx.x];
}

__global__ void k_prep(const int* __restrict__ rowptr, const int* __restrict__ deg,
                       int* __restrict__ cursor, float* __restrict__ invdeg, int N) {
    int i = blockIdx.x * blockDim.x + threadIdx.x;
    if (i < N) {
        cursor[i] = rowptr[i];
        int d = deg[i];
        invdeg[i] = 1.0f / (float)max(d, 1);
    }
}

__global__ void k_fill(const int* __restrict__ src, const int* __restrict__ dst,
                       int* __restrict__ cursor, int* __restrict__ srcs, int E) {
    int e = blockIdx.x * blockDim.x + threadIdx.x;
    if (e < E) {
        int p = atomicAdd(&cursor[dst[e]], 1);
        srcs[p] = src[e];
    }
}

// ---------------- mean aggregation: warp per node, float4 lanes ----------------
__global__ void k_aggregate(const float* __restrict__ h, const int* __restrict__ rowptr,
                            const int* __restrict__ srcs, const float* __restrict__ invdeg,
                            float* __restrict__ agg, int N) {
    int node = blockIdx.x * (blockDim.x >> 5) + (threadIdx.x >> 5);
    if (node >= N) return;
    int lane = threadIdx.x & 31;
    float ax = 0.f, ay = 0.f, az = 0.f, aw = 0.f;
    int e0 = rowptr[node], e1 = rowptr[node + 1];
    for (int e = e0; e < e1; e++) {
        int s = __ldg(&srcs[e]);
        float4 v = *(const float4*)(h + (size_t)s * D + lane * 4);
        ax += v.x; ay += v.y; az += v.z; aw += v.w;
    }
    float id = invdeg[node];
    *(float4*)(agg + (size_t)node * D + lane * 4) = make_float4(ax * id, ay * id, az * id, aw * id);
}

// ---------------- fused GEMM(+GEMM) + bias + relu + layernorm + residual ----------------
// out[m,n] = A1[m,:] @ W1[n,:] (+ A2[m,:] @ W2[n,:]) + bias[n], then optional
// relu -> LN(g,b) -> +resid. Block: 64 rows x 128 cols, 256 threads.
// Thread (warp wy, lane x): rows wy*8+r (r<8), cols x*4+c (c<4).
// Each warp owns 8 full rows -> LN via warp shuffles.
__global__ void __launch_bounds__(256, 4)
k_gemm_fused(const float* __restrict__ A1, const float* __restrict__ W1,
             const float* __restrict__ A2, const float* __restrict__ W2,
             const float* __restrict__ bias,
             const float* __restrict__ lng, const float* __restrict__ lnb,
             const float* __restrict__ resid,
             float* __restrict__ out, int M) {
    __shared__ float As[64][16];
    __shared__ float Bs[16][132];
    int tid  = threadIdx.x;
    int lane = tid & 31;
    int wy   = tid >> 5;
    int row0 = blockIdx.x * 64;

    float acc[8][4];
#pragma unroll
    for (int r = 0; r < 8; r++)
#pragma unroll
        for (int c = 0; c < 4; c++) acc[r][c] = 0.f;

    for (int pass = 0; pass < 2; pass++) {
        const float* A = pass ? A2 : A1;
        const float* W = pass ? W2 : W1;
        if (A == nullptr) break;
        for (int k0 = 0; k0 < D; k0 += 16) {
            // A tile: 64x16, one float4 per thread
            {
                int r = tid >> 2, kq = (tid & 3) * 4;
                int grow = row0 + r;
                float4 v = make_float4(0.f, 0.f, 0.f, 0.f);
                if (grow < M) v = *(const float4*)(A + (size_t)grow * D + k0 + kq);
                *(float4*)&As[r][kq] = v;
            }
            // B tile: Bs[k][n] = W[n][k0+k], 2 float4 per thread
            for (int c = tid; c < 512; c += 256) {
                int n = c >> 2, q = (c & 3) * 4;
                float4 v = *(const float4*)(W + (size_t)n * D + k0 + q);
                Bs[q + 0][n] = v.x; Bs[q + 1][n] = v.y;
                Bs[q + 2][n] = v.z; Bs[q + 3][n] = v.w;
            }
            __syncthreads();
#pragma unroll
            for (int k = 0; k < 16; k++) {
                float4 bv = *(const float4*)&Bs[k][lane * 4];
#pragma unroll
                for (int r = 0; r < 8; r++) {
                    float a = As[wy * 8 + r][k];
                    acc[r][0] += a * bv.x;
                    acc[r][1] += a * bv.y;
                    acc[r][2] += a * bv.z;
                    acc[r][3] += a * bv.w;
                }
            }
            __syncthreads();
        }
    }

    // epilogue
    int colbase = lane * 4;
    float4 bz = make_float4(0.f, 0.f, 0.f, 0.f);
    if (bias) bz = *(const float4*)(bias + colbase);
    bool doln = (lng != nullptr);
    float4 g4 = make_float4(1.f, 1.f, 1.f, 1.f), lb4 = make_float4(0.f, 0.f, 0.f, 0.f);
    if (doln) { g4 = *(const float4*)(lng + colbase); lb4 = *(const float4*)(lnb + colbase); }

#pragma unroll
    for (int r = 0; r < 8; r++) {
        int row = row0 + wy * 8 + r;
        if (row >= M) break;  // uniform across the warp
        float v0 = acc[r][0] + bz.x;
        float v1 = acc[r][1] + bz.y;
        float v2 = acc[r][2] + bz.z;
        float v3 = acc[r][3] + bz.w;
        if (doln) {
            v0 = fmaxf(v0, 0.f); v1 = fmaxf(v1, 0.f);
            v2 = fmaxf(v2, 0.f); v3 = fmaxf(v3, 0.f);
            float s = v0 + v1 + v2 + v3;
#pragma unroll
            for (int o = 16; o > 0; o >>= 1) s += __shfl_xor_sync(0xffffffffu, s, o);
            float mu = s * (1.f / 128.f);
            float d0 = v0 - mu, d1 = v1 - mu, d2 = v2 - mu, d3 = v3 - mu;
            float q = d0 * d0 + d1 * d1 + d2 * d2 + d3 * d3;
#pragma unroll
            for (int o = 16; o > 0; o >>= 1) q += __shfl_xor_sync(0xffffffffu, q, o);
            float rs = rsqrtf(q * (1.f / 128.f) + EPSL);
            v0 = d0 * rs * g4.x + lb4.x;
            v1 = d1 * rs * g4.y + lb4.y;
            v2 = d2 * rs * g4.z + lb4.z;
            v3 = d3 * rs * g4.w + lb4.w;
            float4 rz = *(const float4*)(resid + (size_t)row * D + colbase);
            v0 += rz.x; v1 += rz.y; v2 += rz.z; v3 += rz.w;
        }
        *(float4*)(out + (size_t)row * D + colbase) = make_float4(v0, v1, v2, v3);
    }
}

// ---------------- head + reranker mix: warp per node ----------------
__global__ void k_head(const float* __restrict__ h, const float* __restrict__ hw,
                       const float* __restrict__ hb, const float* __restrict__ rer,
                       const float* __restrict__ alpha, float* __restrict__ out, int N) {
    int node = blockIdx.x * (blockDim.x >> 5) + (threadIdx.x >> 5);
    if (node >= N) return;
    int lane = threadIdx.x & 31;
    float4 v = *(const float4*)(h + (size_t)node * D + lane * 4);
    float4 w = *(const float4*)(hw + lane * 4);
    float s = v.x * w.x + v.y * w.y + v.z * w.z + v.w * w.w;
#pragma unroll
    for (int o = 16; o > 0; o >>= 1) s += __shfl_xor_sync(0xffffffffu, s, o);
    if (lane == 0) {
        float gnn = s + hb[0];
        float a = 1.f / (1.f + expf(-alpha[0]));
        out[node] = a * rer[node] + (1.f - a) * gnn;
    }
}

// ---------------- launch ----------------
extern "C" void kernel_launch(void* const* d_in, const int* in_sizes, int n_in,
                              void* d_out, int out_size) {
    const float* x       = (const float*)d_in[0];
    const int*   ei      = (const int*)  d_in[1];
    const float* rer     = (const float*)d_in[2];
    const float* proj_w  = (const float*)d_in[3];
    const float* proj_b  = (const float*)d_in[4];
    const float* lin_l_w = (const float*)d_in[5];
    const float* lin_l_b = (const float*)d_in[6];
    const float* lin_r_w = (const float*)d_in[7];
    const float* ln_g    = (const float*)d_in[8];
    const float* ln_b    = (const float*)d_in[9];
    const float* head_w  = (const float*)d_in[10];
    const float* head_b  = (const float*)d_in[11];
    const float* alpha   = (const float*)d_in[12];

    int N = in_sizes[0] / D;
    int E = in_sizes[1] / 2;
    const int* src = ei;
    const int* dst = ei + E;
    float* out = (float*)d_out;

    float *res, *agg, *h0, *h1, *invdeg;
    int *deg, *rowptr, *cursor, *stmp, *blks, *srcs;
    cudaGetSymbolAddress((void**)&res,    g_res);
    cudaGetSymbolAddress((void**)&agg,    g_agg);
    cudaGetSymbolAddress((void**)&h0,     g_h0);
    cudaGetSymbolAddress((void**)&h1,     g_h1);
    cudaGetSymbolAddress((void**)&invdeg, g_invdeg);
    cudaGetSymbolAddress((void**)&deg,    g_deg);
    cudaGetSymbolAddress((void**)&rowptr, g_rowptr);
    cudaGetSymbolAddress((void**)&cursor, g_cursor);
    cudaGetSymbolAddress((void**)&stmp,   g_scantmp);
    cudaGetSymbolAddress((void**)&blks,   g_blksums);
    cudaGetSymbolAddress((void**)&srcs,   g_srcsorted);

    int nb = (N + 1023) / 1024;

    // CSR build
    k_zero <<<(N + 255) / 256, 256>>>(deg, rowptr, N);
    k_count<<<(E + 255) / 256, 256>>>(dst, deg, E);
    k_scan1<<<nb, 1024>>>(deg, stmp, blks, N);
    k_scan2<<<1, 32>>>(blks, nb);
    k_scan3<<<nb, 1024>>>(stmp, blks, rowptr, N);
    k_prep <<<(N + 255) / 256, 256>>>(rowptr, deg, cursor, invdeg, N);
    k_fill <<<(E + 255) / 256, 256>>>(src, dst, cursor, srcs, E);

    int gemm_blocks = (N + 63) / 64;
    int warp_blocks = (N + 7) / 8;

    // residual = x @ proj_w^T + proj_b
    k_gemm_fused<<<gemm_blocks, 256>>>(x, proj_w, nullptr, nullptr, proj_b,
                                       nullptr, nullptr, nullptr, res, N);

    const float* h_cur = x;
    float* bufs[2] = {h0, h1};
    for (int i = 0; i < 3; i++) {
        float* h_next = bufs[i & 1];
        k_aggregate<<<warp_blocks, 256>>>(h_cur, rowptr, srcs, invdeg, agg, N);
        const float* resid = (i == 0) ? res : h_cur;
        k_gemm_fused<<<gemm_blocks, 256>>>(agg, lin_l_w + (size_t)i * D * D,
                                           h_cur, lin_r_w + (size_t)i * D * D,
                                           lin_l_b + (size_t)i * D,
                                           ln_g + (size_t)i * D, ln_b + (size_t)i * D,
                                           resid, h_next, N);
        h_cur = h_next;
    }

    k_head<<<warp_blocks, 256>>>(h_cur, head_w, head_b, rer, alpha, out, N);
}

// round 2
// speedup vs baseline: 1.1364x; 1.1364x over previous
#include <cuda_runtime.h>
#include <math.h>

#define D 128
#define MAXN 100096
#define MAXE 1600256
#define EPSL 1e-5f

typedef unsigned long long ull;

__device__ __forceinline__ ull bcast2(float x) {
    ull r; asm("mov.b64 %0, {%1, %1};" : "=l"(r) : "f"(x)); return r;
}
__device__ __forceinline__ void ffma2(ull &d, ull a, ull b) {
    asm("fma.rn.f32x2 %0, %1, %2, %0;" : "+l"(d) : "l"(a), "l"(b));
}
__device__ __forceinline__ float2 unpack2(ull v) {
    float2 f; asm("mov.b64 {%0, %1}, %2;" : "=f"(f.x), "=f"(f.y) : "l"(v)); return f;
}

// ---------------- scratch (device globals: no allocation allowed) ----------------
__device__ float g_res[(size_t)MAXN * D];
__device__ float g_agg[(size_t)MAXN * D];
__device__ float g_h0 [(size_t)MAXN * D];
__device__ float g_h1 [(size_t)MAXN * D];
__device__ float g_invdeg[MAXN];
__device__ int   g_deg[MAXN];
__device__ int   g_rowptr[MAXN + 1];
__device__ int   g_cursor[MAXN];
__device__ int   g_scantmp[MAXN];
__device__ int   g_blksums[256];
__device__ int   g_srcsorted[MAXE];

// ---------------- CSR build ----------------
__global__ void k_zero(int* deg, int* rowptr, int N) {
    int i = blockIdx.x * blockDim.x + threadIdx.x;
    if (i < N) deg[i] = 0;
    if (i == 0) rowptr[0] = 0;
}

__global__ void k_count(const int* __restrict__ dst, int* __restrict__ deg, int E) {
    int e = blockIdx.x * blockDim.x + threadIdx.x;
    if (e < E) atomicAdd(&deg[dst[e]], 1);
}

__global__ void k_scan1(const int* __restrict__ deg, int* __restrict__ tmp,
                        int* __restrict__ blks, int N) {
    __shared__ int sm[1024];
    int i = blockIdx.x * 1024 + threadIdx.x;
    int v = (i < N) ? deg[i] : 0;
    sm[threadIdx.x] = v;
    __syncthreads();
    for (int o = 1; o < 1024; o <<= 1) {
        int t = (threadIdx.x >= o) ? sm[threadIdx.x - o] : 0;
        __syncthreads();
        sm[threadIdx.x] += t;
        __syncthreads();
    }
    if (i < N) tmp[i] = sm[threadIdx.x];
    if (threadIdx.x == 1023) blks[blockIdx.x] = sm[1023];
}

__global__ void k_scan2(int* blks, int nb) {
    if (threadIdx.x == 0 && blockIdx.x == 0) {
        int run = 0;
        for (int b = 0; b < nb; b++) { int t = blks[b]; blks[b] = run; run += t; }
    }
}

__global__ void k_scan3(const int* __restrict__ tmp, const int* __restrict__ blks,
                        int* __restrict__ rowptr, int N) {
    int i = blockIdx.x * 1024 + threadIdx.x;
    if (i < N) rowptr[i + 1] = tmp[i] + blks[blockIdx.x];
}

__global__ void k_prep(const int* __restrict__ rowptr, const int* __restrict__ deg,
                       int* __restrict__ cursor, float* __restrict__ invdeg, int N) {
    int i = blockIdx.x * blockDim.x + threadIdx.x;
    if (i < N) {
        cursor[i] = rowptr[i];
        int d = deg[i];
        invdeg[i] = 1.0f / (float)max(d, 1);
    }
}

__global__ void k_fill(const int* __restrict__ src, const int* __restrict__ dst,
                       int* __restrict__ cursor, int* __restrict__ srcs, int E) {
    int e = blockIdx.x * blockDim.x + threadIdx.x;
    if (e < E) {
        int p = atomicAdd(&cursor[dst[e]], 1);
        srcs[p] = src[e];
    }
}

// ---------------- mean aggregation: warp per node, float4 lanes ----------------
__global__ void k_aggregate(const float* __restrict__ h, const int* __restrict__ rowptr,
                            const int* __restrict__ srcs, const float* __restrict__ invdeg,
                            float* __restrict__ agg, int N) {
    int node = blockIdx.x * (blockDim.x >> 5) + (threadIdx.x >> 5);
    if (node >= N) return;
    int lane = threadIdx.x & 31;
    float ax = 0.f, ay = 0.f, az = 0.f, aw = 0.f;
    int e0 = rowptr[node], e1 = rowptr[node + 1];
    for (int e = e0; e < e1; e++) {
        int s = __ldg(&srcs[e]);
        float4 v = *(const float4*)(h + (size_t)s * D + lane * 4);
        ax += v.x; ay += v.y; az += v.z; aw += v.w;
    }
    float id = invdeg[node];
    *(float4*)(agg + (size_t)node * D + lane * 4) = make_float4(ax * id, ay * id, az * id, aw * id);
}

// ---------------- fused GEMM(+GEMM) + bias + relu + layernorm + residual (+head) ----
// out[m,n] = A1[m,:] @ W1[n,:] (+ A2[m,:] @ W2[n,:]) + bias[n], then optional
// relu -> LN(g,b) -> +resid -> optional head dot + reranker mix.
// Block: 64 rows x 128 cols, 256 threads. Warp wy owns rows wy*8..wy*8+7,
// lane owns cols lane*4..+3. Accumulators packed f32x2 over ROW PAIRS:
// acc[p][c] = {out[2p][c], out[2p+1][c]} -> fma.rn.f32x2 (2x fp32 throughput).
__global__ void __launch_bounds__(256, 2)
k_gemm_fused(const float* __restrict__ A1, const float* __restrict__ W1,
             const float* __restrict__ A2, const float* __restrict__ W2,
             const float* __restrict__ bias,
             const float* __restrict__ lng, const float* __restrict__ lnb,
             const float* __restrict__ resid,
             float* __restrict__ out,
             const float* __restrict__ hw, const float* __restrict__ hb,
             const float* __restrict__ rer, const float* __restrict__ alpha,
             float* __restrict__ score, int M) {
    __shared__ __align__(16) float As[16][66];   // As[k][row]  (transposed A tile)
    __shared__ __align__(16) float Bs[16][132];  // Bs[k][col]
    int tid  = threadIdx.x;
    int lane = tid & 31;
    int wy   = tid >> 5;
    int row0 = blockIdx.x * 64;

    ull acc[4][4];  // [row-pair][col]
#pragma unroll
    for (int p = 0; p < 4; p++)
#pragma unroll
        for (int c = 0; c < 4; c++) acc[p][c] = 0ull;

    for (int pass = 0; pass < 2; pass++) {
        const float* A = pass ? A2 : A1;
        const float* W = pass ? W2 : W1;
        if (A == nullptr) break;
        for (int k0 = 0; k0 < D; k0 += 16) {
            // A tile: 64x16 -> transposed As[k][row]
            {
                int r = tid >> 2, kq = (tid & 3) * 4;
                int grow = row0 + r;
                float4 v = make_float4(0.f, 0.f, 0.f, 0.f);
                if (grow < M) v = *(const float4*)(A + (size_t)grow * D + k0 + kq);
                As[kq + 0][r] = v.x; As[kq + 1][r] = v.y;
                As[kq + 2][r] = v.z; As[kq + 3][r] = v.w;
            }
            // B tile: Bs[k][n] = W[n][k0+k]
            for (int c = tid; c < 512; c += 256) {
                int n = c >> 2, q = (c & 3) * 4;
                float4 v = *(const float4*)(W + (size_t)n * D + k0 + q);
                Bs[q + 0][n] = v.x; Bs[q + 1][n] = v.y;
                Bs[q + 2][n] = v.z; Bs[q + 3][n] = v.w;
            }
            __syncthreads();
#pragma unroll
            for (int k = 0; k < 16; k++) {
                float4 bv = *(const float4*)&Bs[k][lane * 4];
                ull bb0 = bcast2(bv.x), bb1 = bcast2(bv.y);
                ull bb2 = bcast2(bv.z), bb3 = bcast2(bv.w);
                const ull* ap = (const ull*)&As[k][wy * 8];  // row pairs, LDS.64 broadcast
#pragma unroll
                for (int p = 0; p < 4; p++) {
                    ull aa = ap[p];
                    ffma2(acc[p][0], aa, bb0);
                    ffma2(acc[p][1], aa, bb1);
                    ffma2(acc[p][2], aa, bb2);
                    ffma2(acc[p][3], aa, bb3);
                }
            }
            __syncthreads();
        }
    }

    // ---------------- epilogue ----------------
    int colbase = lane * 4;
    float4 bz = make_float4(0.f, 0.f, 0.f, 0.f);
    if (bias) bz = *(const float4*)(bias + colbase);
    bool doln = (lng != nullptr);
    float4 g4 = make_float4(1.f, 1.f, 1.f, 1.f), lb4 = make_float4(0.f, 0.f, 0.f, 0.f);
    if (doln) { g4 = *(const float4*)(lng + colbase); lb4 = *(const float4*)(lnb + colbase); }
    float4 w4 = make_float4(0.f, 0.f, 0.f, 0.f);
    if (score) w4 = *(const float4*)(hw + colbase);

#pragma unroll
    for (int r = 0; r < 8; r++) {
        int row = row0 + wy * 8 + r;
        if (row >= M) break;  // uniform across warp
        int p = r >> 1, half = r & 1;
        float2 f0 = unpack2(acc[p][0]);
        float2 f1 = unpack2(acc[p][1]);
        float2 f2 = unpack2(acc[p][2]);
        float2 f3 = unpack2(acc[p][3]);
        float v0 = (half ? f0.y : f0.x) + bz.x;
        float v1 = (half ? f1.y : f1.x) + bz.y;
        float v2 = (half ? f2.y : f2.x) + bz.z;
        float v3 = (half ? f3.y : f3.x) + bz.w;
        if (doln) {
            v0 = fmaxf(v0, 0.f); v1 = fmaxf(v1, 0.f);
            v2 = fmaxf(v2, 0.f); v3 = fmaxf(v3, 0.f);
            float s = v0 + v1 + v2 + v3;
#pragma unroll
            for (int o = 16; o > 0; o >>= 1) s += __shfl_xor_sync(0xffffffffu, s, o);
            float mu = s * (1.f / 128.f);
            float d0 = v0 - mu, d1 = v1 - mu, d2 = v2 - mu, d3 = v3 - mu;
            float q = d0 * d0 + d1 * d1 + d2 * d2 + d3 * d3;
#pragma unroll
            for (int o = 16; o > 0; o >>= 1) q += __shfl_xor_sync(0xffffffffu, q, o);
            float rs = rsqrtf(q * (1.f / 128.f) + EPSL);
            v0 = d0 * rs * g4.x + lb4.x;
            v1 = d1 * rs * g4.y + lb4.y;
            v2 = d2 * rs * g4.z + lb4.z;
            v3 = d3 * rs * g4.w + lb4.w;
            float4 rz = *(const float4*)(resid + (size_t)row * D + colbase);
            v0 += rz.x; v1 += rz.y; v2 += rz.z; v3 += rz.w;
        }
        if (score) {
            // fused head: gnn = h . head_w + head_b; out = a*rer + (1-a)*gnn
            float sd = v0 * w4.x + v1 * w4.y + v2 * w4.z + v3 * w4.w;
#pragma unroll
            for (int o = 16; o > 0; o >>= 1) sd += __shfl_xor_sync(0xffffffffu, sd, o);
            if (lane == 0) {
                float gnn = sd + hb[0];
                float a = 1.f / (1.f + expf(-alpha[0]));
                score[row] = a * rer[row] + (1.f - a) * gnn;
            }
        } else {
            *(float4*)(out + (size_t)row * D + colbase) = make_float4(v0, v1, v2, v3);
        }
    }
}

// ---------------- launch ----------------
extern "C" void kernel_launch(void* const* d_in, const int* in_sizes, int n_in,
                              void* d_out, int out_size) {
    const float* x       = (const float*)d_in[0];
    const int*   ei      = (const int*)  d_in[1];
    const float* rer     = (const float*)d_in[2];
    const float* proj_w  = (const float*)d_in[3];
    const float* proj_b  = (const float*)d_in[4];
    const float* lin_l_w = (const float*)d_in[5];
    const float* lin_l_b = (const float*)d_in[6];
    const float* lin_r_w = (const float*)d_in[7];
    const float* ln_g    = (const float*)d_in[8];
    const float* ln_b    = (const float*)d_in[9];
    const float* head_w  = (const float*)d_in[10];
    const float* head_b  = (const float*)d_in[11];
    const float* alpha   = (const float*)d_in[12];

    int N = in_sizes[0] / D;
    int E = in_sizes[1] / 2;
    const int* src = ei;
    const int* dst = ei + E;
    float* out = (float*)d_out;

    float *res, *agg, *h0, *h1, *invdeg;
    int *deg, *rowptr, *cursor, *stmp, *blks, *srcs;
    cudaGetSymbolAddress((void**)&res,    g_res);
    cudaGetSymbolAddress((void**)&agg,    g_agg);
    cudaGetSymbolAddress((void**)&h0,     g_h0);
    cudaGetSymbolAddress((void**)&h1,     g_h1);
    cudaGetSymbolAddress((void**)&invdeg, g_invdeg);
    cudaGetSymbolAddress((void**)&deg,    g_deg);
    cudaGetSymbolAddress((void**)&rowptr, g_rowptr);
    cudaGetSymbolAddress((void**)&cursor, g_cursor);
    cudaGetSymbolAddress((void**)&stmp,   g_scantmp);
    cudaGetSymbolAddress((void**)&blks,   g_blksums);
    cudaGetSymbolAddress((void**)&srcs,   g_srcsorted);

    int nb = (N + 1023) / 1024;

    // CSR build
    k_zero <<<(N + 255) / 256, 256>>>(deg, rowptr, N);
    k_count<<<(E + 255) / 256, 256>>>(dst, deg, E);
    k_scan1<<<nb, 1024>>>(deg, stmp, blks, N);
    k_scan2<<<1, 32>>>(blks, nb);
    k_scan3<<<nb, 1024>>>(stmp, blks, rowptr, N);
    k_prep <<<(N + 255) / 256, 256>>>(rowptr, deg, cursor, invdeg, N);
    k_fill <<<(E + 255) / 256, 256>>>(src, dst, cursor, srcs, E);

    int gemm_blocks = (N + 63) / 64;
    int warp_blocks = (N + 7) / 8;

    // residual = x @ proj_w^T + proj_b
    k_gemm_fused<<<gemm_blocks, 256>>>(x, proj_w, nullptr, nullptr, proj_b,
                                       nullptr, nullptr, nullptr, res,
                                       nullptr, nullptr, nullptr, nullptr, nullptr, N);

    const float* h_cur = x;
    float* bufs[2] = {h0, h1};
    for (int i = 0; i < 3; i++) {
        float* h_next = bufs[i & 1];
        k_aggregate<<<warp_blocks, 256>>>(h_cur, rowptr, srcs, invdeg, agg, N);
        const float* resid = (i == 0) ? res : h_cur;
        bool last = (i == 2);
        k_gemm_fused<<<gemm_blocks, 256>>>(agg, lin_l_w + (size_t)i * D * D,
                                           h_cur, lin_r_w + (size_t)i * D * D,
                                           lin_l_b + (size_t)i * D,
                                           ln_g + (size_t)i * D, ln_b + (size_t)i * D,
                                           resid,
                                           last ? nullptr : h_next,
                                           last ? head_w : nullptr,
                                           last ? head_b : nullptr,
                                           last ? rer    : nullptr,
                                           last ? alpha  : nullptr,
                                           last ? out    : nullptr, N);
        h_cur = h_next;
    }
}